// round 16
// baseline (speedup 1.0000x reference)
#include <cuda_runtime.h>
#include <cuda_fp16.h>
#include <cstdint>
#include <math.h>

#define N_TOK 4096
#define DIM   2048
#define FF    1024
#define NE    16
#define CAP   4096

// half-buffer offsets (in halves)
#define OXH  0ull
#define ORG  (8ull  << 20)
#define ORW1 (40ull << 20)
#define ORW2 (72ull << 20)
#define OSG  (104ull << 20)
#define OSW1 (108ull << 20)
#define OSW2 (112ull << 20)

__device__ int    g_cnt[NE];
__device__ int    g_list[NE * CAP];
__device__ float  g_wt[NE * CAP];
__device__ __half g_half[116ull << 20];
__device__ __half g_hh[(size_t)NE * CAP * FF];    // routed hidden
__device__ __half g_hs[(size_t)N_TOK * 2 * FF];   // shared hidden

// ---------- helpers ----------
__device__ __forceinline__ uint32_t smem_u32(const void* p) {
    uint32_t a;
    asm("{ .reg .u64 t; cvta.to.shared.u64 t, %1; cvt.u32.u64 %0, t; }" : "=r"(a) : "l"(p));
    return a;
}
__device__ __forceinline__ void cp16(uint32_t dst, const void* src) {
    asm volatile("cp.async.cg.shared.global [%0], [%1], 16;" :: "r"(dst), "l"(src));
}
__device__ __forceinline__ void ldm4(uint32_t* r, uint32_t a) {
    asm volatile("ldmatrix.sync.aligned.m8n8.x4.shared.b16 {%0,%1,%2,%3}, [%4];"
                 : "=r"(r[0]), "=r"(r[1]), "=r"(r[2]), "=r"(r[3]) : "r"(a));
}
__device__ __forceinline__ void ldm4t(uint32_t* r, uint32_t a) {
    asm volatile("ldmatrix.sync.aligned.m8n8.x4.trans.shared.b16 {%0,%1,%2,%3}, [%4];"
                 : "=r"(r[0]), "=r"(r[1]), "=r"(r[2]), "=r"(r[3]) : "r"(a));
}
__device__ __forceinline__ void mma16(float* d, const uint32_t* a, uint32_t b0, uint32_t b1) {
    asm volatile("mma.sync.aligned.m16n8k16.row.col.f32.f16.f16.f32 "
                 "{%0,%1,%2,%3},{%4,%5,%6,%7},{%8,%9},{%0,%1,%2,%3};"
                 : "+f"(d[0]), "+f"(d[1]), "+f"(d[2]), "+f"(d[3])
                 : "r"(a[0]), "r"(a[1]), "r"(a[2]), "r"(a[3]), "r"(b0), "r"(b1));
}
__device__ __forceinline__ float gelu_exact(float v) {
    return 0.5f * v * (1.0f + erff(v * 0.70710678118654752440f));
}
#define COMMIT() asm volatile("cp.async.commit_group;" ::: "memory")
#define WAIT1()  asm volatile("cp.async.wait_group 1;" ::: "memory")

// ---------- conversions ----------
__device__ __forceinline__ void cvt4(const float* s, size_t si, size_t dofs) {
    float4 v = *(const float4*)(s + si);
    __half2* d = (__half2*)(g_half + dofs + si);
    d[0] = __floats2half2_rn(v.x, v.y);
    d[1] = __floats2half2_rn(v.z, v.w);
}
__global__ void cvt_shared_kernel(const float* __restrict__ x, const float* __restrict__ sg,
                                  const float* __restrict__ sw1) {
    const size_t NX = 8388608ull, NS = 4194304ull;
    size_t i = ((size_t)blockIdx.x * 256 + threadIdx.x) * 4;
    if (i < NX) { cvt4(x, i, OXH); return; }
    i -= NX;
    if (i < NS) { cvt4(sg, i, OSG); return; }
    i -= NS;
    cvt4(sw1, i, OSW1);
}
__global__ void cvt_routed_kernel(const float* __restrict__ rg, const float* __restrict__ rw1) {
    const size_t NR = 33554432ull;
    size_t i = ((size_t)blockIdx.x * 256 + threadIdx.x) * 4;
    if (i < NR) { cvt4(rg, i, ORG); return; }
    i -= NR;
    cvt4(rw1, i, ORW1);
}
__global__ void cvt_dn_kernel(const float* __restrict__ rw2, const float* __restrict__ sw2) {
    const size_t NR = 33554432ull;
    size_t i = ((size_t)blockIdx.x * 256 + threadIdx.x) * 4;
    if (i < NR) { cvt4(rw2, i, ORW2); return; }
    i -= NR;
    cvt4(sw2, i, OSW2);
}
__global__ void copy_x_kernel(const float* __restrict__ x, float* __restrict__ out) {
    size_t i = ((size_t)blockIdx.x * 256 + threadIdx.x) * 4;
    *(float4*)(out + i) = *(const float4*)(x + i);
}

// ---------- router (coalesced, round-12 proven) ----------
__global__ void zero_cnt_kernel() { if (threadIdx.x < NE) g_cnt[threadIdx.x] = 0; }

__global__ void router_kernel(const float* __restrict__ x, const float* __restrict__ wa) {
    int t = (blockIdx.x * blockDim.x + threadIdx.x) >> 5;
    int lane = threadIdx.x & 31;
    if (t >= N_TOK) return;
    const int esub = lane & 15, dhalf = lane >> 4;

    float acc = 0.0f;
    const float* xr = x + (size_t)t * DIM;
    for (int db = 0; db < DIM; db += 32) {
        float xv = xr[db + lane];
#pragma unroll
        for (int i = 0; i < 16; i++) {
            float xj = __shfl_sync(0xffffffffu, xv, 2 * i + dhalf);
            acc += xj * wa[(size_t)(db + 2 * i + dhalf) * NE + esub];
        }
    }
    acc += __shfl_xor_sync(0xffffffffu, acc, 16);
    float aff = 1.0f / (1.0f + expf(-acc));

    float v1 = aff; int i1 = esub;
#pragma unroll
    for (int m = 8; m > 0; m >>= 1) {
        float ov = __shfl_xor_sync(0xffffffffu, v1, m);
        int   oi = __shfl_xor_sync(0xffffffffu, i1, m);
        if (ov > v1 || (ov == v1 && oi < i1)) { v1 = ov; i1 = oi; }
    }
    float v2 = (esub == i1) ? -1e30f : aff; int i2 = esub;
#pragma unroll
    for (int m = 8; m > 0; m >>= 1) {
        float ov = __shfl_xor_sync(0xffffffffu, v2, m);
        int   oi = __shfl_xor_sync(0xffffffffu, i2, m);
        if (ov > v2 || (ov == v2 && oi < i2)) { v2 = ov; i2 = oi; }
    }
    if (lane == 0) {
        float inv = 1.0f / (v1 + v2);
        int q1 = atomicAdd(&g_cnt[i1], 1);
        g_list[i1 * CAP + q1] = t; g_wt[i1 * CAP + q1] = v1 * inv;
        int q2 = atomicAdd(&g_cnt[i2], 1);
        g_list[i2 * CAP + q2] = t; g_wt[i2 * CAP + q2] = v2 * inv;
    }
}

// ---------- NEW: 256-thread up GEMM, 8 warps of 64x32, dual-B 8-col interleave ----------
// MODE 0: shared (writes g_hs), MODE 1: routed (writes g_hh)
template <int MODE>
__global__ void __launch_bounds__(256, 2) up2_kernel(
    const float* __restrict__ bias0, const float* __restrict__ bias1)
{
    constexpr int NCH = DIM / 64;

    const int e = blockIdx.z;
    const int rows = (MODE == 1) ? g_cnt[e] : N_TOK;
    const int m0 = blockIdx.x * 128;
    if (m0 >= rows) return;
    const int n0f = blockIdx.y * 64;

    extern __shared__ char dynsm[];
    __shared__ int s_row[128];
    const int tid = threadIdx.x, wid = tid >> 5, lane = tid & 31;
    const uint32_t sbase = smem_u32(dynsm);

    if (tid < 128) {
        int mm = m0 + tid;
        s_row[tid] = (MODE == 1) ? g_list[e * CAP + (mm < rows ? mm : m0)] : mm;
    }
    __syncthreads();

    // ---- A loader: row = (tid>>3)+j*32, seg = tid&7 (full 128B per row coalescing) ----
    const int aseg = tid & 7, ar0 = tid >> 3;
    int rix[4];
#pragma unroll
    for (int j = 0; j < 4; j++) rix[j] = s_row[ar0 + j * 32];
    const uint32_t a_dst0 = (uint32_t)(ar0 * 128 + ((aseg * 16) ^ ((ar0 & 7) << 4)));

    // ---- B loader: krow = tid>>2, c16 = (tid&3)*4 + j; 8-col G/W interleave ----
    const int bk = tid >> 2, bn16 = tid & 3;
    const __half* G = g_half + (MODE == 0 ? OSG : ORG) + (size_t)e * DIM * FF + n0f + bn16 * 16;
    const __half* W = g_half + (MODE == 0 ? OSW1 : ORW1) + (size_t)e * DIM * FF + n0f + bn16 * 16;
    uint32_t b_dst[4];
#pragma unroll
    for (int j = 0; j < 4; j++) {
        int c16 = bn16 * 4 + j;
        b_dst[j] = (uint32_t)(16384 + bk * 256 + ((c16 * 16) ^ ((bk & 7) << 4)));
    }

#define ISSUE(k0g, buf) do { \
    uint32_t sB_ = sbase + (uint32_t)(buf) * 32768u; \
    _Pragma("unroll") \
    for (int j = 0; j < 4; j++) { \
        cp16(sB_ + a_dst0 + (uint32_t)j * 4096u, \
             g_half + OXH + (size_t)rix[j] * DIM + (k0g) + aseg * 8); \
        const __half* bsrc = ((j & 1) ? W : G) + (j >> 1) * 8 + (size_t)((k0g) + bk) * FF; \
        cp16(sB_ + b_dst[j], bsrc); \
    } \
} while (0)

    // ---- fragments: warp (wm,wn), 64x32 tile ----
    const int wm = wid & 1, wn = wid >> 1;       // wn 0..3
    const int m_off = wm * 64;
    uint32_t aoffc[4], axorl[4];
#pragma unroll
    for (int mi = 0; mi < 4; mi++) {
        int ar = m_off + mi * 16 + (lane & 15);
        aoffc[mi] = (uint32_t)(ar * 128);
        axorl[mi] = (uint32_t)((ar & 7) << 4);
    }
    const uint32_t akp = (uint32_t)((lane >> 4) * 16);
    const int kr0 = ((lane >> 3) & 1) * 8 + (lane & 7);
    const int noct = (lane >> 4) & 1;
    uint32_t boffc[2];
#pragma unroll
    for (int g = 0; g < 2; g++) {
        int nb = wn * 32 + g * 16;
        uint32_t nbyte = (uint32_t)((nb + noct * 8) * 2);
        boffc[g] = 16384u + (uint32_t)(kr0 * 256) + (nbyte ^ (uint32_t)((kr0 & 7) << 4));
    }

    float acc[16][4];
#pragma unroll
    for (int i = 0; i < 16; i++)
#pragma unroll
        for (int j = 0; j < 4; j++) acc[i][j] = 0.0f;

    ISSUE(0, 0);  COMMIT();
    ISSUE(64, 1); COMMIT();
    for (int it = 0; it < NCH; it++) {
        WAIT1();
        __syncthreads();
        if (it + 2 < NCH) ISSUE((it + 2) * 64, (it + 2) % 3);
        COMMIT();
        const uint32_t sb = sbase + (uint32_t)(it % 3) * 32768u;
#pragma unroll
        for (int ks = 0; ks < 4; ks++) {
            uint32_t af[4][4];
#pragma unroll
            for (int mi = 0; mi < 4; mi++)
                ldm4(af[mi], sb + aoffc[mi] + (((uint32_t)(ks * 32) + akp) ^ axorl[mi]));
            uint32_t bf[2][4];
#pragma unroll
            for (int g = 0; g < 2; g++)
                ldm4t(bf[g], sb + boffc[g] + (uint32_t)(ks * 4096));
#pragma unroll
            for (int mi = 0; mi < 4; mi++)
#pragma unroll
                for (int nt = 0; nt < 4; nt++)
                    mma16(acc[mi * 4 + nt], af[mi],
                          bf[nt >> 1][(nt & 1) * 2], bf[nt >> 1][(nt & 1) * 2 + 1]);
        }
    }
#undef ISSUE

    // ---- epilogue: nt even = G (C1), nt odd = W1 (C2); pairs (0,1),(2,3) ----
    const int rbase = lane >> 2;
    const int cbase = (lane & 3) * 2;
#pragma unroll
    for (int mi = 0; mi < 4; mi++) {
#pragma unroll
        for (int h = 0; h < 2; h++) {
            const int m = m0 + m_off + mi * 16 + rbase + h * 8;
            if (m >= rows) continue;
#pragma unroll
            for (int p = 0; p < 2; p++) {
                const int f = n0f + wn * 16 + p * 8 + cbase;
                float c1a = acc[mi * 4 + p * 2][h * 2 + 0] + bias0[(size_t)e * FF + f];
                float c1b = acc[mi * 4 + p * 2][h * 2 + 1] + bias0[(size_t)e * FF + f + 1];
                float c2a = acc[mi * 4 + p * 2 + 1][h * 2 + 0] + bias1[(size_t)e * FF + f];
                float c2b = acc[mi * 4 + p * 2 + 1][h * 2 + 1] + bias1[(size_t)e * FF + f + 1];
                __half2 hv = __floats2half2_rn(gelu_exact(c1a) * c2a, gelu_exact(c1b) * c2b);
                __half* dst = (MODE == 0)
                    ? (g_hs + (size_t)m * (2 * FF) + (size_t)e * FF + f)
                    : (g_hh + ((size_t)e * CAP + m) * FF + f);
                *(__half2*)dst = hv;
            }
        }
    }
}

// ---------- down GEMM (round-14 proven, modes 2/3 only) ----------
template <int MODE>
__global__ void __launch_bounds__(128, 2) mma_kernel(
    const float* __restrict__ bias0, float* __restrict__ outp)
{
    constexpr int KT  = (MODE == 3) ? FF : DIM;
    constexpr int LDA = (MODE == 3) ? FF : DIM;
    constexpr int NCH = KT / 64;

    const int e = blockIdx.z;
    const int rows = (MODE == 3) ? g_cnt[e] : N_TOK;
    const int m0 = blockIdx.x * 128;
    if (m0 >= rows) return;
    const int n0f = blockIdx.y * 128;

    extern __shared__ char dynsm[];
    __shared__ int s_row[128];
    const int tid = threadIdx.x, wid = tid >> 5, lane = tid & 31;
    const uint32_t sbase = smem_u32(dynsm);

    s_row[tid] = m0 + tid;
    __syncthreads();

    const __half* Ah = (MODE == 2) ? g_hs : g_hh + (size_t)e * CAP * FF;
    int rix[8];
#pragma unroll
    for (int i = 0; i < 8; i++) rix[i] = s_row[(tid >> 3) + i * 16];

    const int c = tid & 15;
    const __half* Bb = g_half + (MODE == 2 ? OSW2 : (ORW2 + (size_t)e * FF * DIM)) + n0f + c * 8;
    const int akseg = tid & 7, arow = tid >> 3, kroww = tid >> 4;
    const uint32_t a_dst = (uint32_t)(arow * 128 + ((akseg * 16) ^ ((arow & 7) << 4)));
    const uint32_t b_dst = (uint32_t)(16384 + kroww * 256 + ((c * 16) ^ (kroww << 4)));

#define DISSUE(k0g, buf) do { \
    uint32_t sB_ = sbase + (uint32_t)(buf) * 32768u; \
    _Pragma("unroll") \
    for (int i_ = 0; i_ < 8; i_++) { \
        cp16(sB_ + a_dst + (uint32_t)i_ * 2048u, Ah + (size_t)rix[i_] * LDA + (k0g) + akseg * 8); \
        cp16(sB_ + b_dst + (uint32_t)i_ * 2048u, Bb + (size_t)((k0g) + kroww + i_ * 8) * DIM); \
    } \
} while (0)

    const int wm = wid & 1, wn = wid >> 1;
    const int m_off = wm * 64;
    uint32_t aoffc[4], axorl[4];
#pragma unroll
    for (int mi = 0; mi < 4; mi++) {
        int ar = m_off + mi * 16 + (lane & 15);
        aoffc[mi] = (uint32_t)(ar * 128);
        axorl[mi] = (uint32_t)((ar & 7) << 4);
    }
    const uint32_t akp = (uint32_t)((lane >> 4) * 16);
    const int kr0 = ((lane >> 3) & 1) * 8 + (lane & 7);
    const int noct = (lane >> 4) & 1;
    uint32_t boffc[4];
#pragma unroll
    for (int g = 0; g < 4; g++) {
        int nb = wn * 64 + g * 16;
        uint32_t nbyte = (uint32_t)((nb + noct * 8) * 2);
        boffc[g] = 16384u + (uint32_t)(kr0 * 256) + (nbyte ^ (uint32_t)((kr0 & 7) << 4));
    }

    float acc[32][4];
#pragma unroll
    for (int i = 0; i < 32; i++)
#pragma unroll
        for (int j = 0; j < 4; j++) acc[i][j] = 0.0f;

    DISSUE(0, 0);  COMMIT();
    DISSUE(64, 1); COMMIT();
    for (int it = 0; it < NCH; it++) {
        WAIT1();
        __syncthreads();
        if (it + 2 < NCH) DISSUE((it + 2) * 64, (it + 2) % 3);
        COMMIT();
        const uint32_t sb = sbase + (uint32_t)(it % 3) * 32768u;
#pragma unroll
        for (int ks = 0; ks < 4; ks++) {
            uint32_t af[4][4];
#pragma unroll
            for (int mi = 0; mi < 4; mi++)
                ldm4(af[mi], sb + aoffc[mi] + (((uint32_t)(ks * 32) + akp) ^ axorl[mi]));
            uint32_t bf[4][4];
#pragma unroll
            for (int g = 0; g < 4; g++)
                ldm4t(bf[g], sb + boffc[g] + (uint32_t)(ks * 4096));
#pragma unroll
            for (int mi = 0; mi < 4; mi++)
#pragma unroll
                for (int nt = 0; nt < 8; nt++)
                    mma16(acc[mi * 8 + nt], af[mi],
                          bf[nt >> 1][(nt & 1) * 2], bf[nt >> 1][(nt & 1) * 2 + 1]);
        }
    }
#undef DISSUE

    const int rbase = lane >> 2;
    const int cbase = (lane & 3) * 2;
#pragma unroll
    for (int mi = 0; mi < 4; mi++) {
#pragma unroll
        for (int h = 0; h < 2; h++) {
            const int m = m0 + m_off + mi * 16 + rbase + h * 8;
            if (m >= rows) continue;
            int tok; float w;
            if (MODE == 3) { tok = g_list[e * CAP + m]; w = g_wt[e * CAP + m]; }
            else           { tok = m; w = 1.0f; }
            float* orow = outp + (size_t)tok * DIM;
#pragma unroll
            for (int nt = 0; nt < 8; nt++) {
                const int d = n0f + wn * 64 + nt * 8 + cbase;
                float v0 = acc[mi * 8 + nt][h * 2 + 0];
                float v1 = acc[mi * 8 + nt][h * 2 + 1];
                if (MODE == 2) {
                    atomicAdd(orow + d,     v0 + bias0[d]     + bias0[DIM + d]);
                    atomicAdd(orow + d + 1, v1 + bias0[d + 1] + bias0[DIM + d + 1]);
                } else {
                    atomicAdd(orow + d,     w * (v0 + bias0[(size_t)e * DIM + d]));
                    atomicAdd(orow + d + 1, w * (v1 + bias0[(size_t)e * DIM + d + 1]));
                }
            }
        }
    }
}

// ---------- launch (round-14 proven DAG) ----------
extern "C" void kernel_launch(void* const* d_in, const int* in_sizes, int n_in,
                              void* d_out, int out_size) {
    const float* x   = (const float*)d_in[0];
    const float* wa  = (const float*)d_in[1];
    const float* rg  = (const float*)d_in[2];
    const float* rgb = (const float*)d_in[3];
    const float* rw1 = (const float*)d_in[4];
    const float* rb1 = (const float*)d_in[5];
    const float* rw2 = (const float*)d_in[6];
    const float* rb2 = (const float*)d_in[7];
    const float* sg  = (const float*)d_in[8];
    const float* sgb = (const float*)d_in[9];
    const float* sw1 = (const float*)d_in[10];
    const float* sb1 = (const float*)d_in[11];
    const float* sw2 = (const float*)d_in[12];
    const float* sb2 = (const float*)d_in[13];
    float* out = (float*)d_out;

    static cudaStream_t s1 = nullptr, s2 = nullptr;
    static cudaEvent_t evF = nullptr, evCS = nullptr, evCR = nullptr,
                       evCD = nullptr, evB = nullptr;
    static bool attr_done = false;
    if (!s1) {
        cudaStreamCreateWithFlags(&s1, cudaStreamNonBlocking);
        cudaStreamCreateWithFlags(&s2, cudaStreamNonBlocking);
        cudaEventCreateWithFlags(&evF, cudaEventDisableTiming);
        cudaEventCreateWithFlags(&evCS, cudaEventDisableTiming);
        cudaEventCreateWithFlags(&evCR, cudaEventDisableTiming);
        cudaEventCreateWithFlags(&evCD, cudaEventDisableTiming);
        cudaEventCreateWithFlags(&evB, cudaEventDisableTiming);
    }
    const int smem = 3 * 32768;
    if (!attr_done) {
        cudaFuncSetAttribute(up2_kernel<0>, cudaFuncAttributeMaxDynamicSharedMemorySize, smem);
        cudaFuncSetAttribute(up2_kernel<1>, cudaFuncAttributeMaxDynamicSharedMemorySize, smem);
        cudaFuncSetAttribute(mma_kernel<2>, cudaFuncAttributeMaxDynamicSharedMemorySize, smem);
        cudaFuncSetAttribute(mma_kernel<3>, cudaFuncAttributeMaxDynamicSharedMemorySize, smem);
        attr_done = true;
    }

    // fork s1 (routed chain) off main
    cudaEventRecord(evF, 0);
    cudaStreamWaitEvent(s1, evF, 0);
    zero_cnt_kernel<<<1, 32, 0, s1>>>();                 // 0
    router_kernel<<<N_TOK / 4, 128, 0, s1>>>(x, wa);     // 1

    // main: minimal conversions to unblock the shared chain
    cvt_shared_kernel<<<16384, 256>>>(x, sg, sw1);       // 2
    cudaEventRecord(evCS, 0);

    // main: shared up GEMM (launch 3 — ncu-profiled)
    up2_kernel<0><<<dim3(N_TOK / 128, FF / 64, 2), 256, smem>>>(sgb, sb1);

    // s2: remaining conversions + out seeding (after cvt_shared; overlaps up)
    cudaStreamWaitEvent(s2, evCS, 0);
    cvt_routed_kernel<<<65536, 256, 0, s2>>>(rg, rw1);   // 4
    cudaEventRecord(evCR, s2);
    cvt_dn_kernel<<<36864, 256, 0, s2>>>(rw2, sw2);      // 5
    copy_x_kernel<<<8192, 256, 0, s2>>>(x, out);         // 6
    cudaEventRecord(evCD, s2);

    // s1 (routed chain): up then down, concurrent with the shared chain
    cudaStreamWaitEvent(s1, evCR, 0);
    up2_kernel<1><<<dim3(CAP / 128, FF / 64, NE), 256, smem, s1>>>(rgb, rb1);           // 7
    cudaStreamWaitEvent(s1, evCD, 0);
    mma_kernel<3><<<dim3(CAP / 128, DIM / 128, NE), 128, smem, s1>>>(rb2, out);         // 8
    cudaEventRecord(evB, s1);

    // main (shared chain): down
    cudaStreamWaitEvent(0, evCD, 0);
    mma_kernel<2><<<dim3(N_TOK / 128, DIM / 128, 1), 128, smem>>>(sb2, out);            // 9

    // join routed chain back into main for capture closure
    cudaStreamWaitEvent(0, evB, 0);
}

// round 17
// speedup vs baseline: 1.1355x; 1.1355x over previous
#include <cuda_runtime.h>
#include <cuda_fp16.h>
#include <cstdint>
#include <math.h>

#define N_TOK 4096
#define DIM   2048
#define FF    1024
#define NE    16
#define CAP   4096

// half-buffer offsets (in halves)
#define OXH  0ull
#define ORG  (8ull  << 20)
#define ORW1 (40ull << 20)
#define ORW2 (72ull << 20)
#define OSG  (104ull << 20)
#define OSW1 (108ull << 20)
#define OSW2 (112ull << 20)

__device__ int    g_cnt[NE];
__device__ int    g_list[NE * CAP];
__device__ float  g_wt[NE * CAP];
__device__ __half g_half[116ull << 20];
__device__ __half g_hh[(size_t)NE * CAP * FF];    // routed hidden
__device__ __half g_hs[(size_t)N_TOK * 2 * FF];   // shared hidden

// ---------- helpers ----------
__device__ __forceinline__ uint32_t smem_u32(const void* p) {
    uint32_t a;
    asm("{ .reg .u64 t; cvta.to.shared.u64 t, %1; cvt.u32.u64 %0, t; }" : "=r"(a) : "l"(p));
    return a;
}
__device__ __forceinline__ void cp16(uint32_t dst, const void* src) {
    asm volatile("cp.async.cg.shared.global [%0], [%1], 16;" :: "r"(dst), "l"(src));
}
__device__ __forceinline__ void ldm4(uint32_t* r, uint32_t a) {
    asm volatile("ldmatrix.sync.aligned.m8n8.x4.shared.b16 {%0,%1,%2,%3}, [%4];"
                 : "=r"(r[0]), "=r"(r[1]), "=r"(r[2]), "=r"(r[3]) : "r"(a));
}
__device__ __forceinline__ void ldm4t(uint32_t* r, uint32_t a) {
    asm volatile("ldmatrix.sync.aligned.m8n8.x4.trans.shared.b16 {%0,%1,%2,%3}, [%4];"
                 : "=r"(r[0]), "=r"(r[1]), "=r"(r[2]), "=r"(r[3]) : "r"(a));
}
__device__ __forceinline__ void mma16(float* d, const uint32_t* a, uint32_t b0, uint32_t b1) {
    asm volatile("mma.sync.aligned.m16n8k16.row.col.f32.f16.f16.f32 "
                 "{%0,%1,%2,%3},{%4,%5,%6,%7},{%8,%9},{%0,%1,%2,%3};"
                 : "+f"(d[0]), "+f"(d[1]), "+f"(d[2]), "+f"(d[3])
                 : "r"(a[0]), "r"(a[1]), "r"(a[2]), "r"(a[3]), "r"(b0), "r"(b1));
}
__device__ __forceinline__ void red2(float* p, float a, float b) {
    asm volatile("red.global.add.v2.f32 [%0], {%1,%2};" :: "l"(p), "f"(a), "f"(b) : "memory");
}
__device__ __forceinline__ float gelu_exact(float v) {
    return 0.5f * v * (1.0f + erff(v * 0.70710678118654752440f));
}
#define COMMIT() asm volatile("cp.async.commit_group;" ::: "memory")
#define WAIT1()  asm volatile("cp.async.wait_group 1;" ::: "memory")

// ---------- conversions ----------
__device__ __forceinline__ void cvt4(const float* s, size_t si, size_t dofs) {
    float4 v = *(const float4*)(s + si);
    __half2* d = (__half2*)(g_half + dofs + si);
    d[0] = __floats2half2_rn(v.x, v.y);
    d[1] = __floats2half2_rn(v.z, v.w);
}
__global__ void cvt_shared_kernel(const float* __restrict__ x, const float* __restrict__ sg,
                                  const float* __restrict__ sw1) {
    const size_t NX = 8388608ull, NS = 4194304ull;
    size_t i = ((size_t)blockIdx.x * 256 + threadIdx.x) * 4;
    if (i < NX) { cvt4(x, i, OXH); return; }
    i -= NX;
    if (i < NS) { cvt4(sg, i, OSG); return; }
    i -= NS;
    cvt4(sw1, i, OSW1);
}
__global__ void cvt_routed_kernel(const float* __restrict__ rg, const float* __restrict__ rw1) {
    const size_t NR = 33554432ull;
    size_t i = ((size_t)blockIdx.x * 256 + threadIdx.x) * 4;
    if (i < NR) { cvt4(rg, i, ORG); return; }
    i -= NR;
    cvt4(rw1, i, ORW1);
}
__global__ void cvt_dn_kernel(const float* __restrict__ rw2, const float* __restrict__ sw2) {
    const size_t NR = 33554432ull;
    size_t i = ((size_t)blockIdx.x * 256 + threadIdx.x) * 4;
    if (i < NR) { cvt4(rw2, i, ORW2); return; }
    i -= NR;
    cvt4(sw2, i, OSW2);
}
__global__ void copy_x_kernel(const float* __restrict__ x, float* __restrict__ out) {
    size_t i = ((size_t)blockIdx.x * 256 + threadIdx.x) * 4;
    *(float4*)(out + i) = *(const float4*)(x + i);
}

// ---------- router (coalesced, round-12 proven) ----------
__global__ void zero_cnt_kernel() { if (threadIdx.x < NE) g_cnt[threadIdx.x] = 0; }

__global__ void router_kernel(const float* __restrict__ x, const float* __restrict__ wa) {
    int t = (blockIdx.x * blockDim.x + threadIdx.x) >> 5;
    int lane = threadIdx.x & 31;
    if (t >= N_TOK) return;
    const int esub = lane & 15, dhalf = lane >> 4;

    float acc = 0.0f;
    const float* xr = x + (size_t)t * DIM;
    for (int db = 0; db < DIM; db += 32) {
        float xv = xr[db + lane];
#pragma unroll
        for (int i = 0; i < 16; i++) {
            float xj = __shfl_sync(0xffffffffu, xv, 2 * i + dhalf);
            acc += xj * wa[(size_t)(db + 2 * i + dhalf) * NE + esub];
        }
    }
    acc += __shfl_xor_sync(0xffffffffu, acc, 16);
    float aff = 1.0f / (1.0f + expf(-acc));

    float v1 = aff; int i1 = esub;
#pragma unroll
    for (int m = 8; m > 0; m >>= 1) {
        float ov = __shfl_xor_sync(0xffffffffu, v1, m);
        int   oi = __shfl_xor_sync(0xffffffffu, i1, m);
        if (ov > v1 || (ov == v1 && oi < i1)) { v1 = ov; i1 = oi; }
    }
    float v2 = (esub == i1) ? -1e30f : aff; int i2 = esub;
#pragma unroll
    for (int m = 8; m > 0; m >>= 1) {
        float ov = __shfl_xor_sync(0xffffffffu, v2, m);
        int   oi = __shfl_xor_sync(0xffffffffu, i2, m);
        if (ov > v2 || (ov == v2 && oi < i2)) { v2 = ov; i2 = oi; }
    }
    if (lane == 0) {
        float inv = 1.0f / (v1 + v2);
        int q1 = atomicAdd(&g_cnt[i1], 1);
        g_list[i1 * CAP + q1] = t; g_wt[i1 * CAP + q1] = v1 * inv;
        int q2 = atomicAdd(&g_cnt[i2], 1);
        g_list[i2 * CAP + q2] = t; g_wt[i2 * CAP + q2] = v2 * inv;
    }
}

// ---------- fp16 warp-MMA GEMM: 128x128 CTA, 4 warps of 64x64 (round-14 proven) ----------
// modes: 0 up-shared (writes g_hs), 1 up-routed (writes g_hh),
//        2 down-shared (red out), 3 down-routed (red out)
template <int MODE>
__global__ void __launch_bounds__(128, 2) mma_kernel(
    const float* __restrict__ bias0, const float* __restrict__ bias1,
    float* __restrict__ outp)
{
    constexpr bool UP = (MODE <= 1);
    constexpr int KT  = (MODE == 3) ? FF : DIM;
    constexpr int LDA = (MODE == 3) ? FF : DIM;   // MODE2: g_hs row = 2*FF = DIM
    constexpr int LDB = UP ? FF : DIM;
    constexpr int NCH = KT / 64;

    const int e = blockIdx.z;
    const int rows = (MODE == 1 || MODE == 3) ? g_cnt[e] : N_TOK;
    const int m0 = blockIdx.x * 128;
    if (m0 >= rows) return;
    const int n0f = blockIdx.y * (UP ? 64 : 128);

    extern __shared__ char dynsm[];
    __shared__ int s_row[128];
    const int tid = threadIdx.x, wid = tid >> 5, lane = tid & 31;
    const uint32_t sbase = smem_u32(dynsm);

    {
        int mm = m0 + tid;
        s_row[tid] = (MODE == 1) ? g_list[e * CAP + (mm < rows ? mm : m0)] : mm;
    }
    __syncthreads();

    const __half* Ah = UP ? (g_half + OXH)
                          : (MODE == 2 ? g_hs : g_hh + (size_t)e * CAP * FF);
    int rix[8];
#pragma unroll
    for (int i = 0; i < 8; i++) rix[i] = s_row[(tid >> 3) + i * 16];

    const int c = tid & 15;
    const __half* Bb;
    if (UP) {
        const __half* G = g_half + (MODE == 0 ? OSG : ORG) + (size_t)e * DIM * FF;
        const __half* W = g_half + (MODE == 0 ? OSW1 : ORW1) + (size_t)e * DIM * FF;
        int f = n0f + (c >> 2) * 16 + (c & 1) * 8;
        Bb = (((c >> 1) & 1) ? W : G) + f;
    } else {
        Bb = g_half + (MODE == 2 ? OSW2 : (ORW2 + (size_t)e * FF * DIM)) + n0f + c * 8;
    }
    const int akseg = tid & 7, arow = tid >> 3, kroww = tid >> 4;
    const uint32_t a_dst = (uint32_t)(arow * 128 + ((akseg * 16) ^ ((arow & 7) << 4)));
    const uint32_t b_dst = (uint32_t)(16384 + kroww * 256 + ((c * 16) ^ (kroww << 4)));

#define ISSUE(k0g, buf) do { \
    uint32_t sB_ = sbase + (uint32_t)(buf) * 32768u; \
    _Pragma("unroll") \
    for (int i_ = 0; i_ < 8; i_++) { \
        cp16(sB_ + a_dst + (uint32_t)i_ * 2048u, Ah + (size_t)rix[i_] * LDA + (k0g) + akseg * 8); \
        cp16(sB_ + b_dst + (uint32_t)i_ * 2048u, Bb + (size_t)((k0g) + kroww + i_ * 8) * LDB); \
    } \
} while (0)

    const int wm = wid & 1, wn = wid >> 1;
    const int m_off = wm * 64;
    uint32_t aoffc[4], axorl[4];
#pragma unroll
    for (int mi = 0; mi < 4; mi++) {
        int ar = m_off + mi * 16 + (lane & 15);
        aoffc[mi] = (uint32_t)(ar * 128);
        axorl[mi] = (uint32_t)((ar & 7) << 4);
    }
    const uint32_t akp = (uint32_t)((lane >> 4) * 16);
    const int kr0 = ((lane >> 3) & 1) * 8 + (lane & 7);
    const int noct = (lane >> 4) & 1;
    uint32_t boffc[4];
#pragma unroll
    for (int g = 0; g < 4; g++) {
        int nb = wn * 64 + g * 16;
        uint32_t nbyte = (uint32_t)((nb + noct * 8) * 2);
        boffc[g] = 16384u + (uint32_t)(kr0 * 256) + (nbyte ^ (uint32_t)((kr0 & 7) << 4));
    }

    float acc[32][4];
#pragma unroll
    for (int i = 0; i < 32; i++)
#pragma unroll
        for (int j = 0; j < 4; j++) acc[i][j] = 0.0f;

    ISSUE(0, 0);  COMMIT();
    ISSUE(64, 1); COMMIT();
    for (int it = 0; it < NCH; it++) {
        WAIT1();
        __syncthreads();
        if (it + 2 < NCH) ISSUE((it + 2) * 64, (it + 2) % 3);
        COMMIT();
        const uint32_t sb = sbase + (uint32_t)(it % 3) * 32768u;
#pragma unroll
        for (int ks = 0; ks < 4; ks++) {
            uint32_t af[4][4];
#pragma unroll
            for (int mi = 0; mi < 4; mi++)
                ldm4(af[mi], sb + aoffc[mi] + (((uint32_t)(ks * 32) + akp) ^ axorl[mi]));
            uint32_t bf[4][4];
#pragma unroll
            for (int g = 0; g < 4; g++)
                ldm4t(bf[g], sb + boffc[g] + (uint32_t)(ks * 4096));
#pragma unroll
            for (int mi = 0; mi < 4; mi++)
#pragma unroll
                for (int nt = 0; nt < 8; nt++)
                    mma16(acc[mi * 8 + nt], af[mi],
                          bf[nt >> 1][(nt & 1) * 2], bf[nt >> 1][(nt & 1) * 2 + 1]);
        }
    }
#undef ISSUE

    const int rbase = lane >> 2;
    const int cbase = (lane & 3) * 2;
    if (UP) {
#pragma unroll
        for (int mi = 0; mi < 4; mi++) {
#pragma unroll
            for (int h = 0; h < 2; h++) {
                const int m = m0 + m_off + mi * 16 + rbase + h * 8;
                if (m >= rows) continue;
#pragma unroll
                for (int gi = 0; gi < 4; gi++) {
                    const int g = (gi & 1) + (gi >> 1) * 4;  // 0,1,4,5
                    const int f = n0f + wn * 32 + (g >> 2) * 16 + (g & 1) * 8 + cbase;
                    float c1a = acc[mi * 8 + g][h * 2 + 0] + bias0[(size_t)e * FF + f];
                    float c1b = acc[mi * 8 + g][h * 2 + 1] + bias0[(size_t)e * FF + f + 1];
                    float c2a = acc[mi * 8 + g + 2][h * 2 + 0] + bias1[(size_t)e * FF + f];
                    float c2b = acc[mi * 8 + g + 2][h * 2 + 1] + bias1[(size_t)e * FF + f + 1];
                    __half2 hv = __floats2half2_rn(gelu_exact(c1a) * c2a, gelu_exact(c1b) * c2b);
                    __half* dst = (MODE == 0)
                        ? (g_hs + (size_t)m * (2 * FF) + (size_t)e * FF + f)
                        : (g_hh + ((size_t)e * CAP + m) * FF + f);
                    *(__half2*)dst = hv;
                }
            }
        }
    } else {
#pragma unroll
        for (int mi = 0; mi < 4; mi++) {
#pragma unroll
            for (int h = 0; h < 2; h++) {
                const int m = m0 + m_off + mi * 16 + rbase + h * 8;
                if (m >= rows) continue;
                int tok; float w;
                if (MODE == 3) { tok = g_list[e * CAP + m]; w = g_wt[e * CAP + m]; }
                else           { tok = m; w = 1.0f; }
                float* orow = outp + (size_t)tok * DIM;
#pragma unroll
                for (int nt = 0; nt < 8; nt++) {
                    const int d = n0f + wn * 64 + nt * 8 + cbase;
                    float v0 = acc[mi * 8 + nt][h * 2 + 0];
                    float v1 = acc[mi * 8 + nt][h * 2 + 1];
                    if (MODE == 2) {
                        red2(orow + d, v0 + bias0[d] + bias0[DIM + d],
                                       v1 + bias0[d + 1] + bias0[DIM + d + 1]);
                    } else {
                        red2(orow + d, w * (v0 + bias0[(size_t)e * DIM + d]),
                                       w * (v1 + bias0[(size_t)e * DIM + d + 1]));
                    }
                }
            }
        }
    }
}

// ---------- launch: two parallel GEMM chains (round-14 proven DAG) ----------
extern "C" void kernel_launch(void* const* d_in, const int* in_sizes, int n_in,
                              void* d_out, int out_size) {
    const float* x   = (const float*)d_in[0];
    const float* wa  = (const float*)d_in[1];
    const float* rg  = (const float*)d_in[2];
    const float* rgb = (const float*)d_in[3];
    const float* rw1 = (const float*)d_in[4];
    const float* rb1 = (const float*)d_in[5];
    const float* rw2 = (const float*)d_in[6];
    const float* rb2 = (const float*)d_in[7];
    const float* sg  = (const float*)d_in[8];
    const float* sgb = (const float*)d_in[9];
    const float* sw1 = (const float*)d_in[10];
    const float* sb1 = (const float*)d_in[11];
    const float* sw2 = (const float*)d_in[12];
    const float* sb2 = (const float*)d_in[13];
    float* out = (float*)d_out;

    static cudaStream_t s1 = nullptr, s2 = nullptr;
    static cudaEvent_t evF = nullptr, evCS = nullptr, evCR = nullptr,
                       evCD = nullptr, evB = nullptr;
    static bool attr_done = false;
    if (!s1) {
        cudaStreamCreateWithFlags(&s1, cudaStreamNonBlocking);
        cudaStreamCreateWithFlags(&s2, cudaStreamNonBlocking);
        cudaEventCreateWithFlags(&evF, cudaEventDisableTiming);
        cudaEventCreateWithFlags(&evCS, cudaEventDisableTiming);
        cudaEventCreateWithFlags(&evCR, cudaEventDisableTiming);
        cudaEventCreateWithFlags(&evCD, cudaEventDisableTiming);
        cudaEventCreateWithFlags(&evB, cudaEventDisableTiming);
    }
    const int smem = 3 * 32768;
    if (!attr_done) {
        cudaFuncSetAttribute(mma_kernel<0>, cudaFuncAttributeMaxDynamicSharedMemorySize, smem);
        cudaFuncSetAttribute(mma_kernel<1>, cudaFuncAttributeMaxDynamicSharedMemorySize, smem);
        cudaFuncSetAttribute(mma_kernel<2>, cudaFuncAttributeMaxDynamicSharedMemorySize, smem);
        cudaFuncSetAttribute(mma_kernel<3>, cudaFuncAttributeMaxDynamicSharedMemorySize, smem);
        attr_done = true;
    }

    // fork s1 (routed chain) and s2 (prep chain) off main
    cudaEventRecord(evF, 0);
    cudaStreamWaitEvent(s1, evF, 0);
    cudaStreamWaitEvent(s2, evF, 0);

    zero_cnt_kernel<<<1, 32, 0, s1>>>();                 // 0
    router_kernel<<<N_TOK / 4, 128, 0, s1>>>(x, wa);     // 1

    // s2: out seeding first (depends only on x), small
    copy_x_kernel<<<8192, 256, 0, s2>>>(x, out);         // 2

    // main: minimal conversions to unblock the shared chain
    cvt_shared_kernel<<<16384, 256>>>(x, sg, sw1);       // 3
    cudaEventRecord(evCS, 0);

    // main: shared up GEMM
    mma_kernel<0><<<dim3(N_TOK / 128, FF / 64, 2), 128, smem>>>(sgb, sb1, nullptr);

    // s2: remaining conversions (after cvt_shared to avoid DRAM contention on it)
    cudaStreamWaitEvent(s2, evCS, 0);
    cvt_routed_kernel<<<65536, 256, 0, s2>>>(rg, rw1);
    cudaEventRecord(evCR, s2);
    cvt_dn_kernel<<<36864, 256, 0, s2>>>(rw2, sw2);
    cudaEventRecord(evCD, s2);

    // s1 (routed chain): up then down, concurrent with the shared chain
    cudaStreamWaitEvent(s1, evCR, 0);
    mma_kernel<1><<<dim3(CAP / 128, FF / 64, NE), 128, smem, s1>>>(rgb, rb1, nullptr);
    cudaStreamWaitEvent(s1, evCD, 0);
    mma_kernel<3><<<dim3(CAP / 128, DIM / 128, NE), 128, smem, s1>>>(rb2, nullptr, out);
    cudaEventRecord(evB, s1);

    // main (shared chain): down
    cudaStreamWaitEvent(0, evCD, 0);
    mma_kernel<2><<<dim3(N_TOK / 128, DIM / 128, 1), 128, smem>>>(sb2, nullptr, out);

    // join routed chain back into main for capture closure
    cudaStreamWaitEvent(0, evB, 0);
}